// round 15
// baseline (speedup 1.0000x reference)
#include <cuda_runtime.h>
#include <cuda_bf16.h>
#include <cstdint>

#define NQ 16384
#define NS 4096
#define NP 16
#define D2C 256
#define CIN 512
#define COUT 256
#define BIGD 1e8f
#define WEPS 1e-8f
#define BNEPS 1e-5f

// ---------------- scratch (static device globals; no allocation) -------------
// bf16 operand planes, CHUNK-MAJOR swizzled layout:
//   byte_off(n,k) = (k>>5)*(ROWS*64) + n*64 + ((((k>>3)&3) ^ ((n>>1)&3))<<4) + (k&7)*2
__device__ __align__(16) __nv_bfloat16 g_fAh[NQ * CIN];   // feats hi plane
__device__ __align__(16) __nv_bfloat16 g_fAl[NQ * CIN];   // feats lo plane
__device__ __align__(16) __nv_bfloat16 g_x1h[NQ * COUT];  // layer1-act hi plane
__device__ __align__(16) __nv_bfloat16 g_x1l[NQ * COUT];  // layer1-act lo plane
__device__ __align__(16) __nv_bfloat16 g_wh[CIN * COUT + COUT * COUT]; // w0|w1 hi
__device__ __align__(16) __nv_bfloat16 g_wl[CIN * COUT + COUT * COUT]; // w0|w1 lo
__device__ __align__(16) float g_f2t[NS * D2C];     // points2 transposed [S][256]
__device__ __align__(16) float g_y[NQ * COUT];      // pre-BN layer1
__device__ __align__(16) float g_y2[NQ * COUT];     // pre-BN layer2
__device__ __align__(16) float4 g_b2[NS];           // bucketed xyz2 (x,y,z,|T|^2)
__device__ int g_b2i[NS];
__device__ __align__(16) float4 g_b1[NQ];           // bucketed xyz1 (x,y,z,origN)
__device__ int g_qp[NQ];
__device__ int g_cnt1[NP], g_cnt2[NP], g_fill1[NP], g_fill2[NP];  // zeroed at graph end
__device__ float g_ps[256 * COUT], g_pq[256 * COUT];  // per GEMM-CTA BN partials
__device__ float g_scale[COUT], g_shift[COUT];
__device__ int g_sem1, g_sem2;

// ---------------- helpers -----------------------------------------------------
__device__ __forceinline__ uint32_t smem_u32(const void* p) {
    uint32_t a;
    asm("{ .reg .u64 t; cvta.to.shared.u64 t, %1; cvt.u32.u64 %0, t; }" : "=r"(a) : "l"(p));
    return a;
}
__device__ __forceinline__ uint32_t packbf2(float a, float b) {
    uint32_t ua = (uint32_t)__bfloat16_as_ushort(__float2bfloat16_rn(a));
    uint32_t ub = (uint32_t)__bfloat16_as_ushort(__float2bfloat16_rn(b));
    return ua | (ub << 16);
}
__device__ __forceinline__ void split4(float4 v, uint2& hi, uint2& lo) {
    __nv_bfloat16 hx = __float2bfloat16_rn(v.x), hy = __float2bfloat16_rn(v.y);
    __nv_bfloat16 hz = __float2bfloat16_rn(v.z), hw = __float2bfloat16_rn(v.w);
    hi.x = (uint32_t)__bfloat16_as_ushort(hx) | ((uint32_t)__bfloat16_as_ushort(hy) << 16);
    hi.y = (uint32_t)__bfloat16_as_ushort(hz) | ((uint32_t)__bfloat16_as_ushort(hw) << 16);
    lo.x = packbf2(v.x - __bfloat162float(hx), v.y - __bfloat162float(hy));
    lo.y = packbf2(v.z - __bfloat162float(hz), v.w - __bfloat162float(hw));
}
__device__ __forceinline__ long plane_off(int ROWS, int n, int k) {
    return (long)(k >> 5) * (ROWS * 64) + (long)n * 64 +
           ((((k >> 3) & 3) ^ ((n >> 1) & 3)) << 4) + (k & 7) * 2;
}
__device__ __forceinline__ int detect_is64(const int* pid1w, int t) {
    int flag = (pid1w[2 * (t & 255) + 1] != 0);
    int any = __syncthreads_or(flag);
    return !any;
}

// ============================================================================
// PREP: fused splitW | points1 transpose+split | points2 transpose | count
// ============================================================================
#define PB_SPLITW 192
#define PB_TSPLIT 4096
#define PB_TRANS  1024
#define PB_COUNT  64
#define PB_TOTAL  (PB_SPLITW + PB_TSPLIT + PB_TRANS + PB_COUNT)

__global__ __launch_bounds__(256) void k_prep(const float* __restrict__ w0,
                                              const float* __restrict__ w1,
                                              const float* __restrict__ points1,
                                              const float* __restrict__ points2,
                                              const int* __restrict__ pid1w,
                                              const int* __restrict__ pid2w) {
    __shared__ float tile[32][33];
    __shared__ int h1[NP], h2[NP];
    int b = blockIdx.x;
    int tid = threadIdx.x;
    if (b < PB_SPLITW) {
        int i = b * 256 + tid;       // quad index
        float4 v;
        int j, k;
        long base;
        if (i < 32768) {             // w0: [256][512]
            v = ((const float4*)w0)[i];
            j = i >> 7; k = (i & 127) * 4;
            base = plane_off(COUT, j, k);
        } else {                     // w1: [256][256], after 256KB
            int ii = i - 32768;
            v = ((const float4*)w1)[ii];
            j = ii >> 6; k = (ii & 63) * 4;
            base = 262144 + plane_off(COUT, j, k);
        }
        uint2 hi, lo; split4(v, hi, lo);
        *(uint2*)((char*)g_wh + base) = hi;
        *(uint2*)((char*)g_wl + base) = lo;
    } else if (b < PB_SPLITW + PB_TSPLIT) {
        int bb = b - PB_SPLITW;
        int c0 = (bb & 511) * 32, r0 = (bb >> 9) * 32;
        int tx = tid & 31, ty = tid >> 5;
#pragma unroll
        for (int i = 0; i < 4; i++)
            tile[ty + 8 * i][tx] = points1[(r0 + ty + 8 * i) * NQ + c0 + tx];
        __syncthreads();
#pragma unroll
        for (int i = 0; i < 4; i++) {
            int n = c0 + ty + 8 * i, k = r0 + tx;
            float v = tile[tx][ty + 8 * i];
            __nv_bfloat16 h = __float2bfloat16_rn(v);
            long off = plane_off(NQ, n, k);
            *(__nv_bfloat16*)((char*)g_fAh + off) = h;
            *(__nv_bfloat16*)((char*)g_fAl + off) = __float2bfloat16_rn(v - __bfloat162float(h));
        }
    } else if (b < PB_SPLITW + PB_TSPLIT + PB_TRANS) {
        int bb = b - PB_SPLITW - PB_TSPLIT;
        int c0 = (bb & 127) * 32, r0 = (bb >> 7) * 32;
        int tx = tid & 31, ty = tid >> 5;
#pragma unroll
        for (int i = 0; i < 4; i++)
            tile[ty + 8 * i][tx] = points2[(r0 + ty + 8 * i) * NS + c0 + tx];
        __syncthreads();
#pragma unroll
        for (int i = 0; i < 4; i++)
            g_f2t[(c0 + ty + 8 * i) * (long)D2C + r0 + tx] = tile[tx][ty + 8 * i];
    } else {
        int bb = b - (PB_SPLITW + PB_TSPLIT + PB_TRANS);
        if (tid < NP) { h1[tid] = 0; h2[tid] = 0; }
        int is64 = detect_is64(pid1w, tid);
        int i = bb * 256 + tid;
        int p1 = is64 ? pid1w[2 * i] : pid1w[i];
        atomicAdd(&h1[p1], 1);
        if (i < NS) {
            int p2 = is64 ? pid2w[2 * i] : pid2w[i];
            atomicAdd(&h2[p2], 1);
        }
        __syncthreads();
        if (tid < NP) {
            if (h1[tid]) atomicAdd(&g_cnt1[tid], h1[tid]);
            if (h2[tid]) atomicAdd(&g_cnt2[tid], h2[tid]);
        }
    }
}

// ---------------- scatter ------------------------------------------------------
__global__ void k_scatter(const float* __restrict__ x1, const float* __restrict__ x2,
                          const int* __restrict__ pid1w, const int* __restrict__ pid2w) {
    __shared__ int h1[NP], h2[NP], b1[NP], b2[NP], r1[NP], r2[NP];
    int t = threadIdx.x;
    if (t < NP) { h1[t] = 0; h2[t] = 0; r1[t] = 0; r2[t] = 0; }
    int is64 = detect_is64(pid1w, t);
    int i = blockIdx.x * 256 + t;
    int p1 = is64 ? pid1w[2 * i] : pid1w[i];
    atomicAdd(&h1[p1], 1);
    int p2 = -1;
    if (i < NS) {
        p2 = is64 ? pid2w[2 * i] : pid2w[i];
        atomicAdd(&h2[p2], 1);
    }
    __syncthreads();
    if (t < NP) {
        int o1 = 0, o2 = 0;
        for (int j = 0; j < t; j++) { o1 += g_cnt1[j]; o2 += g_cnt2[j]; }
        b1[t] = o1 + atomicAdd(&g_fill1[t], h1[t]);
        b2[t] = o2 + atomicAdd(&g_fill2[t], h2[t]);
    }
    __syncthreads();
    {
        int pos = b1[p1] + atomicAdd(&r1[p1], 1);
        g_b1[pos] = make_float4(x1[i], x1[NQ + i], x1[2 * NQ + i], __int_as_float(i));
        g_qp[pos] = p1;
    }
    if (i < NS) {
        int pos = b2[p2] + atomicAdd(&r2[p2], 1);
        float tx = x2[i], ty = x2[NS + i], tz = x2[2 * NS + i];
        float t2 = fmaf(tx, tx, fmaf(ty, ty, tz * tz));
        g_b2[pos] = make_float4(tx, ty, tz, t2);
        g_b2i[pos] = i;
    }
}

// ---------------- fused KNN + interpolation -----------------------------------
__device__ __forceinline__ void top4_ins(float d, int j,
                                         float& d0, float& d1, float& d2, float& d3,
                                         int& j0, int& j1, int& j2, int& j3) {
    if (d < d3) {
        if (d < d1) {
            if (d < d0) { d3 = d2; j3 = j2; d2 = d1; j2 = j1; d1 = d0; j1 = j0; d0 = d; j0 = j; }
            else        { d3 = d2; j3 = j2; d2 = d1; j2 = j1; d1 = d; j1 = j; }
        } else {
            if (d < d2) { d3 = d2; j3 = j2; d2 = d; j2 = j; }
            else        { d3 = d; j3 = j; }
        }
    }
}

__global__ __launch_bounds__(256) void k_knn_interp() {
    __shared__ int soff[NP + 1];
    if (threadIdx.x == 0) {
        int s = 0; soff[0] = 0;
        for (int p = 0; p < NP; p++) { s += g_cnt2[p]; soff[p + 1] = s; }
    }
    __syncthreads();
    int t = blockIdx.x * blockDim.x + threadIdx.x;
    int lane = threadIdx.x & 31;
    int q = t >> 2;
    int l4 = t & 3;
    float4 Q = g_b1[q];
    int p = g_qp[q];
    int s0 = soff[p], s1 = soff[p + 1];
    const float FINF = __int_as_float(0x7f800000);
    const float nnx = -2.f * Q.x, nny = -2.f * Q.y, nnz = -2.f * Q.z;
    float d0 = FINF, d1 = FINF, d2 = FINF, d3 = FINF;
    int j0 = -1, j1 = -1, j2 = -1, j3 = -1;
    int j = s0 + l4;
    for (; j + 4 < s1; j += 8) {
        float4 T = g_b2[j];
        float4 U = g_b2[j + 4];
        float d = fmaf(nnx, T.x, fmaf(nny, T.y, fmaf(nnz, T.z, T.w)));
        float e = fmaf(nnx, U.x, fmaf(nny, U.y, fmaf(nnz, U.z, U.w)));
        top4_ins(d, j, d0, d1, d2, d3, j0, j1, j2, j3);
        top4_ins(e, j + 4, d0, d1, d2, d3, j0, j1, j2, j3);
    }
    if (j < s1) {
        float4 T = g_b2[j];
        float d = fmaf(nnx, T.x, fmaf(nny, T.y, fmaf(nnz, T.z, T.w)));
        top4_ins(d, j, d0, d1, d2, d3, j0, j1, j2, j3);
    }
#pragma unroll
    for (int m = 1; m <= 2; m <<= 1) {
        float e0 = __shfl_xor_sync(0xffffffffu, d0, m);
        float e1 = __shfl_xor_sync(0xffffffffu, d1, m);
        float e2 = __shfl_xor_sync(0xffffffffu, d2, m);
        float e3 = __shfl_xor_sync(0xffffffffu, d3, m);
        int k0 = __shfl_xor_sync(0xffffffffu, j0, m);
        int k1 = __shfl_xor_sync(0xffffffffu, j1, m);
        int k2 = __shfl_xor_sync(0xffffffffu, j2, m);
        int k3 = __shfl_xor_sync(0xffffffffu, j3, m);
        top4_ins(e0, k0, d0, d1, d2, d3, j0, j1, j2, j3);
        top4_ins(e1, k1, d0, d1, d2, d3, j0, j1, j2, j3);
        top4_ins(e2, k2, d0, d1, d2, d3, j0, j1, j2, j3);
        top4_ins(e3, k3, d0, d1, d2, d3, j0, j1, j2, j3);
    }
    int fi0 = 0, fi1 = 0, fi2 = 0;
    float fw0 = 0.f, fw1 = 0.f, fw2 = 0.f;
    if (l4 == 0) {
        int cand[4] = { j0, j1, j2, j3 };
        float de[4];
#pragma unroll
        for (int c = 0; c < 4; c++) {
            if (cand[c] >= 0) {
                float4 T = g_b2[cand[c]];
                float dx = Q.x - T.x, dy = Q.y - T.y, dz = Q.z - T.z;
                de[c] = fmaf(dx, dx, fmaf(dy, dy, dz * dz));
            } else de[c] = FINF;
        }
#pragma unroll
        for (int r = 0; r < 3; r++) {
            int best = r;
#pragma unroll
            for (int c = r + 1; c < 4; c++) if (de[c] < de[best]) best = c;
            float td = de[r]; de[r] = de[best]; de[best] = td;
            int tj = cand[r]; cand[r] = cand[best]; cand[best] = tj;
        }
        fi0 = (cand[0] >= 0) ? g_b2i[cand[0]] : 0;
        fi1 = (cand[1] >= 0) ? g_b2i[cand[1]] : 0;
        fi2 = (cand[2] >= 0) ? g_b2i[cand[2]] : 0;
        float e0 = de[0], e1 = de[1], e2 = de[2];
        if (!(e0 < FINF)) { fi0 = 0;   e0 = BIGD; }
        if (!(e1 < FINF)) { fi1 = fi0; e1 = BIGD; }
        if (!(e2 < FINF)) { fi2 = fi0; e2 = BIGD; }
        float w0 = 1.0f / (e0 + WEPS);
        float w1 = 1.0f / (e1 + WEPS);
        float w2 = 1.0f / (e2 + WEPS);
        float inv = 1.0f / (w0 + w1 + w2);
        fw0 = w0 * inv; fw1 = w1 * inv; fw2 = w2 * inv;
    }
#pragma unroll 1
    for (int qi = 0; qi < 8; qi++) {
        int src = 4 * qi;
        int i0 = __shfl_sync(0xffffffffu, fi0, src);
        int i1 = __shfl_sync(0xffffffffu, fi1, src);
        int i2 = __shfl_sync(0xffffffffu, fi2, src);
        float w0 = __shfl_sync(0xffffffffu, fw0, src);
        float w1 = __shfl_sync(0xffffffffu, fw1, src);
        float w2 = __shfl_sync(0xffffffffu, fw2, src);
        int n = __shfl_sync(0xffffffffu, __float_as_int(Q.w), src);
        const float4* r0 = (const float4*)(g_f2t + (long)i0 * D2C);
        const float4* r1 = (const float4*)(g_f2t + (long)i1 * D2C);
        const float4* r2 = (const float4*)(g_f2t + (long)i2 * D2C);
#pragma unroll
        for (int c = lane; c < D2C / 4; c += 32) {
            float4 a = r0[c], b = r1[c], cc = r2[c];
            float4 v;
            v.x = w0 * a.x + w1 * b.x + w2 * cc.x;
            v.y = w0 * a.y + w1 * b.y + w2 * cc.y;
            v.z = w0 * a.z + w1 * b.z + w2 * cc.z;
            v.w = w0 * a.w + w1 * b.w + w2 * cc.w;
            uint2 hi, lo; split4(v, hi, lo);
            long off = plane_off(NQ, n, 256 + 4 * c);
            *(uint2*)((char*)g_fAh + off) = hi;
            *(uint2*)((char*)g_fAl + off) = lo;
        }
    }
}

// ---------------- BN+ReLU+split of layer1 activations (feeds GEMM2) ----------
__global__ __launch_bounds__(256) void k_bnsplit(const float* __restrict__ Y) {
    int idx = blockIdx.x * 256 + threadIdx.x;
    int n = idx >> 5, k8 = (idx & 31) * 8;
    float4 v0 = *(const float4*)&Y[(long)n * COUT + k8];
    float4 v1 = *(const float4*)&Y[(long)n * COUT + k8 + 4];
    float4 sc0 = *(const float4*)&g_scale[k8],  sh0 = *(const float4*)&g_shift[k8];
    float4 sc1 = *(const float4*)&g_scale[k8 + 4], sh1 = *(const float4*)&g_shift[k8 + 4];
    v0.x = fmaxf(fmaf(v0.x, sc0.x, sh0.x), 0.f);
    v0.y = fmaxf(fmaf(v0.y, sc0.y, sh0.y), 0.f);
    v0.z = fmaxf(fmaf(v0.z, sc0.z, sh0.z), 0.f);
    v0.w = fmaxf(fmaf(v0.w, sc0.w, sh0.w), 0.f);
    v1.x = fmaxf(fmaf(v1.x, sc1.x, sh1.x), 0.f);
    v1.y = fmaxf(fmaf(v1.y, sc1.y, sh1.y), 0.f);
    v1.z = fmaxf(fmaf(v1.z, sc1.z, sh1.z), 0.f);
    v1.w = fmaxf(fmaf(v1.w, sc1.w, sh1.w), 0.f);
    uint2 h0, l0, h1, l1;
    split4(v0, h0, l0);
    split4(v1, h1, l1);
    long off = plane_off(NQ, n, k8);
    *(uint4*)((char*)g_x1h + off) = make_uint4(h0.x, h0.y, h1.x, h1.y);
    *(uint4*)((char*)g_x1l + off) = make_uint4(l0.x, l0.y, l1.x, l1.y);
}

// ============================================================================
// HMMA bf16x3 GEMM, cp.async.bulk fills (2-stage ring) + fused BN-finalize
// CTA = 64M x 256N, 256 threads / 8 warps (2x4 grid, warp tile 32x64).
// smem/stage: [Ah 4K][Al 4K][Bh 16K][Bl 16K] = 40K; 2 CTAs co-resident per SM.
// ============================================================================
#define HBUF 40960
#define HSMEM (1024 + 2 * HBUF)
#define NCTA (NQ / 64)          // 256

__device__ __forceinline__ void bulk_g2s(uint32_t dst, const void* src, uint32_t bytes,
                                         uint32_t mbar) {
    asm volatile(
        "cp.async.bulk.shared::cluster.global.mbarrier::complete_tx::bytes [%0], [%1], %2, [%3];"
        :: "r"(dst), "l"(src), "r"(bytes), "r"(mbar) : "memory");
}
__device__ __forceinline__ void mbar_wait(uint32_t addr, uint32_t parity) {
    asm volatile(
        "{\n\t.reg .pred P;\n"
        "LW_%=:\n\t"
        "mbarrier.try_wait.parity.acquire.cta.shared::cta.b64 P, [%0], %1, 0x989680;\n\t"
        "@P bra LD_%=;\n\t"
        "bra LW_%=;\n"
        "LD_%=:\n\t}"
        :: "r"(addr), "r"(parity) : "memory");
}
__device__ __forceinline__ void ldsm4(uint32_t* r, uint32_t addr) {
    asm volatile("ldmatrix.sync.aligned.m8n8.x4.shared.b16 {%0,%1,%2,%3}, [%4];"
                 : "=r"(r[0]), "=r"(r[1]), "=r"(r[2]), "=r"(r[3]) : "r"(addr));
}
__device__ __forceinline__ void mma16816(float* c, const uint32_t* a, uint32_t b0, uint32_t b1) {
    asm volatile(
        "mma.sync.aligned.m16n8k16.row.col.f32.bf16.bf16.f32 "
        "{%0,%1,%2,%3}, {%4,%5,%6,%7}, {%8,%9}, {%0,%1,%2,%3};"
        : "+f"(c[0]), "+f"(c[1]), "+f"(c[2]), "+f"(c[3])
        : "r"(a[0]), "r"(a[1]), "r"(a[2]), "r"(a[3]), "r"(b0), "r"(b1));
}

template<int KDIM>
__global__ __launch_bounds__(256, 2) void k_hmma(const __nv_bfloat16* __restrict__ Ah,
                                                 const __nv_bfloat16* __restrict__ Al,
                                                 const __nv_bfloat16* __restrict__ Wh,
                                                 const __nv_bfloat16* __restrict__ Wl,
                                                 float* __restrict__ Y,
                                                 const float* __restrict__ gamma,
                                                 const float* __restrict__ beta,
                                                 int* __restrict__ sem) {
    extern __shared__ char sm[];
    const int tid = threadIdx.x;
    const int wid = tid >> 5, lid = tid & 31;
    const int wm = wid >> 2, wn = wid & 3;   // 2x4 warp grid, warp tile 32x64
    const int NCH = KDIM / 32;
    const uint32_t sbase = smem_u32(sm);

    if (tid == 0) {
#pragma unroll
        for (int s = 0; s < 2; s++)
            asm volatile("mbarrier.init.shared.b64 [%0], 1;" :: "r"(sbase + 8 * s) : "memory");
    }
    __syncthreads();

    const char* Ahg = (const char*)Ah + (long)blockIdx.x * 4096;   // + chunk*NQ*64
    const char* Alg = (const char*)Al + (long)blockIdx.x * 4096;
    const char* Whg = (const char*)Wh;                              // + chunk*16384
    const char* Wlg = (const char*)Wl;

    // per-lane ldmatrix bases (64B pitch, seg ^= (row>>1)&3 baked into layout)
    const int aRow = wm * 32 + (lid & 15);
    const uint32_t aOff = (uint32_t)aRow * 64;
    const int xA = (aRow >> 1) & 3;
    const int segA = lid >> 4;
    const int bRow = wn * 64 + (lid & 7) + ((lid >> 4) & 1) * 8;
    const uint32_t bOff = (uint32_t)bRow * 64;
    const int xB = (bRow >> 1) & 3;
    const int segB = (lid >> 3) & 1;

    float acc[2][8][4];
#pragma unroll
    for (int i = 0; i < 2; i++)
#pragma unroll
        for (int jj = 0; jj < 8; jj++)
#pragma unroll
            for (int e = 0; e < 4; e++) acc[i][jj][e] = 0.f;

    auto issue = [&](int c) {
        if (tid == 0) {
            int b = c & 1;
            uint32_t sbuf = sbase + 1024 + (uint32_t)b * HBUF;
            uint32_t mb = sbase + 8 * (uint32_t)b;
            asm volatile("mbarrier.arrive.expect_tx.shared.b64 _, [%0], %1;"
                         :: "r"(mb), "r"(40960u) : "memory");
            bulk_g2s(sbuf,         Ahg + (long)c * (NQ * 64), 4096, mb);
            bulk_g2s(sbuf + 4096,  Alg + (long)c * (NQ * 64), 4096, mb);
            bulk_g2s(sbuf + 8192,  Whg + (long)c * 16384, 16384, mb);
            bulk_g2s(sbuf + 24576, Wlg + (long)c * 16384, 16384, mb);
        }
    };

    issue(0); issue(1);

    for (int c = 0; c < NCH; c++) {
        mbar_wait(sbase + 8 * (uint32_t)(c & 1), (uint32_t)((c >> 1) & 1));

        const uint32_t base = sbase + 1024 + (uint32_t)(c & 1) * HBUF;
#pragma unroll
        for (int ks = 0; ks < 2; ks++) {
            uint32_t aH[8], aL[8];
            const uint32_t aseg = (uint32_t)(((segA + 2 * ks) ^ xA) << 4);
#pragma unroll
            for (int mt = 0; mt < 2; mt++) {
                uint32_t a0 = base + aOff + (uint32_t)mt * 1024 + aseg;
                ldsm4(aH + 4 * mt, a0);
                ldsm4(aL + 4 * mt, a0 + 4096);
            }
            const uint32_t bseg = (uint32_t)(((segB + 2 * ks) ^ xB) << 4);
#pragma unroll
            for (int ng = 0; ng < 4; ng++) {
                uint32_t b0 = base + 8192 + bOff + (uint32_t)ng * 1024 + bseg;
                uint32_t bh[4], bl[4];
                ldsm4(bh, b0);
                ldsm4(bl, b0 + 16384);
#pragma unroll
                for (int mt = 0; mt < 2; mt++) {
                    mma16816(acc[mt][2 * ng],     aH + 4 * mt, bh[0], bh[1]);
                    mma16816(acc[mt][2 * ng + 1], aH + 4 * mt, bh[2], bh[3]);
                }
#pragma unroll
                for (int mt = 0; mt < 2; mt++) {
                    mma16816(acc[mt][2 * ng],     aH + 4 * mt, bl[0], bl[1]);
                    mma16816(acc[mt][2 * ng + 1], aH + 4 * mt, bl[2], bl[3]);
                }
#pragma unroll
                for (int mt = 0; mt < 2; mt++) {
                    mma16816(acc[mt][2 * ng],     aL + 4 * mt, bh[0], bh[1]);
                    mma16816(acc[mt][2 * ng + 1], aL + 4 * mt, bh[2], bh[3]);
                }
            }
        }
        __syncthreads();                 // stage consumed by ALL warps
        if (c + 2 < NCH) issue(c + 2);
    }

    // ---- epilogue: store Y + BN partials (deterministic order) ----
    const int g = lid >> 2, t = lid & 3;
    const int rowbase = blockIdx.x * 64 + wm * 32;
    const int colbase = wn * 64;
#pragma unroll
    for (int mt = 0; mt < 2; mt++) {
#pragma unroll
        for (int nt = 0; nt < 8; nt++) {
            float* c = acc[mt][nt];
            long r0 = (long)(rowbase + mt * 16 + g) * COUT + colbase + nt * 8 + 2 * t;
            *(float2*)&Y[r0] = make_float2(c[0], c[1]);
            *(float2*)&Y[r0 + 8 * COUT] = make_float2(c[2], c[3]);
        }
    }
    float* sm_s = (float*)(sm + 1024);               // [2][256]
    float* sm_q = (float*)(sm + 1024 + 2048);
#pragma unroll
    for (int nt = 0; nt < 8; nt++) {
        float s0 = 0.f, s1 = 0.f, q0 = 0.f, q1 = 0.f;
#pragma unroll
        for (int mt = 0; mt < 2; mt++) {
            float* c = acc[mt][nt];
            s0 += c[0] + c[2];
            s1 += c[1] + c[3];
            q0 += c[0] * c[0] + c[2] * c[2];
            q1 += c[1] * c[1] + c[3] * c[3];
        }
#pragma unroll
        for (int m = 4; m <= 16; m <<= 1) {
            s0 += __shfl_xor_sync(0xffffffffu, s0, m);
            s1 += __shfl_xor_sync(0xffffffffu, s1, m);
            q0 += __shfl_xor_sync(0xffffffffu, q0, m);
            q1 += __shfl_xor_sync(0xffffffffu, q1, m);
        }
        if (g == 0) {
            int col = colbase + nt * 8 + 2 * t;
            sm_s[wm * 256 + col] = s0; sm_s[wm * 256 + col + 1] = s1;
            sm_q[wm * 256 + col] = q0; sm_q[wm * 256 + col + 1] = q1;
        }
    }
    __syncthreads();
    g_ps[blockIdx.x * COUT + tid] = sm_s[tid] + sm_s[256 + tid];
    g_pq[blockIdx.x * COUT + tid] = sm_q[tid] + sm_q[256 + tid];

    // ---- last-CTA BN finalize (deterministic fixed-order reduce) ----
    __shared__ int slast;
    __threadfence();
    __syncthreads();
    if (tid == 0) slast = (atomicAdd(sem, 1) == NCTA - 1);
    __syncthreads();
    if (slast) {
        __threadfence();
        float s = 0.f, q = 0.f;
#pragma unroll 4
        for (int b = 0; b < NCTA; b++) {
            s += g_ps[b * COUT + tid];
            q += g_pq[b * COUT + tid];
        }
        float mean = s * (1.0f / NQ);
        float var = q * (1.0f / NQ) - mean * mean;
        float rstd = rsqrtf(var + BNEPS);
        float sc = gamma[tid] * rstd;
        g_scale[tid] = sc;
        g_shift[tid] = beta[tid] - mean * sc;
        if (tid == 0) *sem = 0;
    }
}

// final: out[o*N + n] = relu(norm(y2[n][o])); also re-zeroes bucket counters
__global__ void k_outtrans(const float* __restrict__ Y, float* __restrict__ out) {
    __shared__ float tile[32][33];
    int n0 = blockIdx.x * 32, o0 = blockIdx.y * 32;
    int tx = threadIdx.x, ty = threadIdx.y;
    if (blockIdx.x == 0 && blockIdx.y == 0 && ty == 0 && tx < NP) {
        g_cnt1[tx] = 0; g_cnt2[tx] = 0; g_fill1[tx] = 0; g_fill2[tx] = 0;
    }
#pragma unroll
    for (int i = 0; i < 4; i++)
        tile[ty + 8 * i][tx] = Y[(long)(n0 + ty + 8 * i) * COUT + o0 + tx];
    __syncthreads();
#pragma unroll
    for (int i = 0; i < 4; i++) {
        int o = o0 + ty + 8 * i;
        float v = fmaf(tile[tx][ty + 8 * i], g_scale[o], g_shift[o]);
        out[(long)o * NQ + n0 + tx] = fmaxf(v, 0.f);
    }
}

// ---------------- launch ------------------------------------------------------
extern "C" void kernel_launch(void* const* d_in, const int* in_sizes, int n_in,
                              void* d_out, int out_size) {
    const float* xyz1 = (const float*)d_in[0];
    const float* xyz2 = (const float*)d_in[1];
    const int* pid1 = (const int*)d_in[2];
    const int* pid2 = (const int*)d_in[3];
    const float* points1 = (const float*)d_in[4];
    const float* points2 = (const float*)d_in[5];
    const float* w0 = (const float*)d_in[6];
    const float* gg0 = (const float*)d_in[8];
    const float* bt0 = (const float*)d_in[9];
    const float* w1 = (const float*)d_in[10];
    const float* gg1 = (const float*)d_in[12];
    const float* bt1 = (const float*)d_in[13];
    float* out = (float*)d_out;

    __nv_bfloat16 *p_fAh, *p_fAl, *p_x1h, *p_x1l, *p_wh, *p_wl;
    float *p_y, *p_y2;
    int *p_sem1, *p_sem2;
    cudaGetSymbolAddress((void**)&p_fAh, g_fAh);
    cudaGetSymbolAddress((void**)&p_fAl, g_fAl);
    cudaGetSymbolAddress((void**)&p_x1h, g_x1h);
    cudaGetSymbolAddress((void**)&p_x1l, g_x1l);
    cudaGetSymbolAddress((void**)&p_wh, g_wh);
    cudaGetSymbolAddress((void**)&p_wl, g_wl);
    cudaGetSymbolAddress((void**)&p_y, g_y);
    cudaGetSymbolAddress((void**)&p_y2, g_y2);
    cudaGetSymbolAddress((void**)&p_sem1, g_sem1);
    cudaGetSymbolAddress((void**)&p_sem2, g_sem2);

    cudaFuncSetAttribute((const void*)k_hmma<CIN>,
                         cudaFuncAttributeMaxDynamicSharedMemorySize, HSMEM);
    cudaFuncSetAttribute((const void*)k_hmma<COUT>,
                         cudaFuncAttributeMaxDynamicSharedMemorySize, HSMEM);

    k_prep<<<PB_TOTAL, 256>>>(w0, w1, points1, points2, pid1, pid2);
    k_scatter<<<NQ / 256, 256>>>(xyz1, xyz2, pid1, pid2);
    k_knn_interp<<<(NQ * 4) / 256, 256>>>();

    // layer 1: 512 -> 256 (64-row CTAs, 2 per SM; BN finalize fused) — idx 3 (profiled)
    k_hmma<CIN><<<NCTA, 256, HSMEM>>>(p_fAh, p_fAl, p_wh, p_wl,
                                      p_y, gg0, bt0, p_sem1);
    // BN+ReLU+split layer1 activations into chunk-major planes
    k_bnsplit<<<NQ * COUT / 8 / 256, 256>>>(p_y);
    // layer 2: 256 -> 256
    k_hmma<COUT><<<NCTA, 256, HSMEM>>>(p_x1h, p_x1l,
                                       (__nv_bfloat16*)((char*)p_wh + 262144),
                                       (__nv_bfloat16*)((char*)p_wl + 262144),
                                       p_y2, gg1, bt1, p_sem2);
    k_outtrans<<<dim3(NQ / 32, COUT / 32), dim3(32, 8)>>>(p_y2, out);
}

// round 17
// speedup vs baseline: 1.2468x; 1.2468x over previous
#include <cuda_runtime.h>
#include <cuda_fp16.h>
#include <cstdint>

#define NQ 16384
#define NS 4096
#define NP 16
#define D2C 256
#define CIN 512
#define COUT 256
#define BIGD 1e8f
#define WEPS 1e-8f
#define BNEPS 1e-5f

// ---------------- scratch (static device globals; no allocation) -------------
// fp16 operand planes, CHUNK-MAJOR swizzled layout:
//   byte_off(n,k) = (k>>5)*(ROWS*64) + n*64 + ((((k>>3)&3) ^ ((n>>1)&3))<<4) + (k&7)*2
__device__ __align__(16) __half g_fAh[NQ * CIN];   // feats hi plane
__device__ __align__(16) __half g_fAl[NQ * CIN];   // feats lo plane (exact residual)
__device__ __align__(16) __half g_x1h[NQ * COUT];  // layer1-act hi plane
__device__ __align__(16) __half g_x1l[NQ * COUT];  // layer1-act lo plane
__device__ __align__(16) __half g_wh[CIN * COUT + COUT * COUT]; // w0|w1 (single fp16 plane)
__device__ __align__(16) float g_f2t[NS * D2C];     // points2 transposed [S][256]
__device__ __align__(16) float g_y[NQ * COUT];      // pre-BN layer1
__device__ __align__(16) float g_y2[NQ * COUT];     // pre-BN layer2
__device__ __align__(16) float4 g_b2[NS];           // bucketed xyz2 (x,y,z,|T|^2)
__device__ int g_b2i[NS];
__device__ __align__(16) float4 g_b1[NQ];           // bucketed xyz1 (x,y,z,origN)
__device__ int g_qp[NQ];
__device__ int g_cnt1[NP], g_cnt2[NP], g_fill1[NP], g_fill2[NP];  // zeroed at graph end
__device__ float g_ps[128 * COUT], g_pq[128 * COUT];
__device__ float g_scale[COUT], g_shift[COUT];
__device__ int g_sem1, g_sem2;

// ---------------- helpers -----------------------------------------------------
__device__ __forceinline__ uint32_t smem_u32(const void* p) {
    uint32_t a;
    asm("{ .reg .u64 t; cvta.to.shared.u64 t, %1; cvt.u32.u64 %0, t; }" : "=r"(a) : "l"(p));
    return a;
}
__device__ __forceinline__ uint32_t packh2(__half a, __half b) {
    return (uint32_t)__half_as_ushort(a) | ((uint32_t)__half_as_ushort(b) << 16);
}
// fp16 split: v = hi + lo with hi = rn(v), lo = rn(v - hi) (residual ~2^-22 v)
__device__ __forceinline__ void split4h(float4 v, uint2& hi, uint2& lo) {
    __half hx = __float2half_rn(v.x), hy = __float2half_rn(v.y);
    __half hz = __float2half_rn(v.z), hw = __float2half_rn(v.w);
    hi.x = packh2(hx, hy);
    hi.y = packh2(hz, hw);
    lo.x = packh2(__float2half_rn(v.x - __half2float(hx)), __float2half_rn(v.y - __half2float(hy)));
    lo.y = packh2(__float2half_rn(v.z - __half2float(hz)), __float2half_rn(v.w - __half2float(hw)));
}
__device__ __forceinline__ long plane_off(int ROWS, int n, int k) {
    return (long)(k >> 5) * (ROWS * 64) + (long)n * 64 +
           ((((k >> 3) & 3) ^ ((n >> 1) & 3)) << 4) + (k & 7) * 2;
}
__device__ __forceinline__ int detect_is64(const int* pid1w, int t) {
    int flag = (pid1w[2 * (t & 255) + 1] != 0);
    int any = __syncthreads_or(flag);
    return !any;
}

// ============================================================================
// PREP: fused roundW | points1 transpose+split | points2 transpose | count
// ============================================================================
#define PB_SPLITW 192
#define PB_TSPLIT 4096
#define PB_TRANS  1024
#define PB_COUNT  64
#define PB_TOTAL  (PB_SPLITW + PB_TSPLIT + PB_TRANS + PB_COUNT)

__global__ __launch_bounds__(256) void k_prep(const float* __restrict__ w0,
                                              const float* __restrict__ w1,
                                              const float* __restrict__ points1,
                                              const float* __restrict__ points2,
                                              const int* __restrict__ pid1w,
                                              const int* __restrict__ pid2w) {
    __shared__ float tile[32][33];
    __shared__ int h1[NP], h2[NP];
    int b = blockIdx.x;
    int tid = threadIdx.x;
    if (b < PB_SPLITW) {
        int i = b * 256 + tid;       // quad index
        float4 v;
        int j, k;
        long base;
        if (i < 32768) {             // w0: [256][512]
            v = ((const float4*)w0)[i];
            j = i >> 7; k = (i & 127) * 4;
            base = plane_off(COUT, j, k);
        } else {                     // w1: [256][256], after 256KB of w0 plane
            int ii = i - 32768;
            v = ((const float4*)w1)[ii];
            j = ii >> 6; k = (ii & 63) * 4;
            base = 262144 + plane_off(COUT, j, k);
        }
        uint2 hi;
        hi.x = packh2(__float2half_rn(v.x), __float2half_rn(v.y));
        hi.y = packh2(__float2half_rn(v.z), __float2half_rn(v.w));
        *(uint2*)((char*)g_wh + base) = hi;
    } else if (b < PB_SPLITW + PB_TSPLIT) {
        int bb = b - PB_SPLITW;
        int c0 = (bb & 511) * 32, r0 = (bb >> 9) * 32;
        int tx = tid & 31, ty = tid >> 5;
#pragma unroll
        for (int i = 0; i < 4; i++)
            tile[ty + 8 * i][tx] = points1[(r0 + ty + 8 * i) * NQ + c0 + tx];
        __syncthreads();
#pragma unroll
        for (int i = 0; i < 4; i++) {
            int n = c0 + ty + 8 * i, k = r0 + tx;
            float v = tile[tx][ty + 8 * i];
            __half h = __float2half_rn(v);
            long off = plane_off(NQ, n, k);
            *(__half*)((char*)g_fAh + off) = h;
            *(__half*)((char*)g_fAl + off) = __float2half_rn(v - __half2float(h));
        }
    } else if (b < PB_SPLITW + PB_TSPLIT + PB_TRANS) {
        int bb = b - PB_SPLITW - PB_TSPLIT;
        int c0 = (bb & 127) * 32, r0 = (bb >> 7) * 32;
        int tx = tid & 31, ty = tid >> 5;
#pragma unroll
        for (int i = 0; i < 4; i++)
            tile[ty + 8 * i][tx] = points2[(r0 + ty + 8 * i) * NS + c0 + tx];
        __syncthreads();
#pragma unroll
        for (int i = 0; i < 4; i++)
            g_f2t[(c0 + ty + 8 * i) * (long)D2C + r0 + tx] = tile[tx][ty + 8 * i];
    } else {
        int bb = b - (PB_SPLITW + PB_TSPLIT + PB_TRANS);
        if (tid < NP) { h1[tid] = 0; h2[tid] = 0; }
        int is64 = detect_is64(pid1w, tid);
        int i = bb * 256 + tid;
        int p1 = is64 ? pid1w[2 * i] : pid1w[i];
        atomicAdd(&h1[p1], 1);
        if (i < NS) {
            int p2 = is64 ? pid2w[2 * i] : pid2w[i];
            atomicAdd(&h2[p2], 1);
        }
        __syncthreads();
        if (tid < NP) {
            if (h1[tid]) atomicAdd(&g_cnt1[tid], h1[tid]);
            if (h2[tid]) atomicAdd(&g_cnt2[tid], h2[tid]);
        }
    }
}

// ---------------- scatter ------------------------------------------------------
__global__ void k_scatter(const float* __restrict__ x1, const float* __restrict__ x2,
                          const int* __restrict__ pid1w, const int* __restrict__ pid2w) {
    __shared__ int h1[NP], h2[NP], b1[NP], b2[NP], r1[NP], r2[NP];
    int t = threadIdx.x;
    if (t < NP) { h1[t] = 0; h2[t] = 0; r1[t] = 0; r2[t] = 0; }
    int is64 = detect_is64(pid1w, t);
    int i = blockIdx.x * 256 + t;
    int p1 = is64 ? pid1w[2 * i] : pid1w[i];
    atomicAdd(&h1[p1], 1);
    int p2 = -1;
    if (i < NS) {
        p2 = is64 ? pid2w[2 * i] : pid2w[i];
        atomicAdd(&h2[p2], 1);
    }
    __syncthreads();
    if (t < NP) {
        int o1 = 0, o2 = 0;
        for (int j = 0; j < t; j++) { o1 += g_cnt1[j]; o2 += g_cnt2[j]; }
        b1[t] = o1 + atomicAdd(&g_fill1[t], h1[t]);
        b2[t] = o2 + atomicAdd(&g_fill2[t], h2[t]);
    }
    __syncthreads();
    {
        int pos = b1[p1] + atomicAdd(&r1[p1], 1);
        g_b1[pos] = make_float4(x1[i], x1[NQ + i], x1[2 * NQ + i], __int_as_float(i));
        g_qp[pos] = p1;
    }
    if (i < NS) {
        int pos = b2[p2] + atomicAdd(&r2[p2], 1);
        float tx = x2[i], ty = x2[NS + i], tz = x2[2 * NS + i];
        float t2 = fmaf(tx, tx, fmaf(ty, ty, tz * tz));
        g_b2[pos] = make_float4(tx, ty, tz, t2);
        g_b2i[pos] = i;
    }
}

// ---------------- fused KNN + interpolation -----------------------------------
__device__ __forceinline__ void top4_ins(float d, int j,
                                         float& d0, float& d1, float& d2, float& d3,
                                         int& j0, int& j1, int& j2, int& j3) {
    if (d < d3) {
        if (d < d1) {
            if (d < d0) { d3 = d2; j3 = j2; d2 = d1; j2 = j1; d1 = d0; j1 = j0; d0 = d; j0 = j; }
            else        { d3 = d2; j3 = j2; d2 = d1; j2 = j1; d1 = d; j1 = j; }
        } else {
            if (d < d2) { d3 = d2; j3 = j2; d2 = d; j2 = j; }
            else        { d3 = d; j3 = j; }
        }
    }
}

__global__ __launch_bounds__(256) void k_knn_interp() {
    __shared__ int soff[NP + 1];
    if (threadIdx.x == 0) {
        int s = 0; soff[0] = 0;
        for (int p = 0; p < NP; p++) { s += g_cnt2[p]; soff[p + 1] = s; }
    }
    __syncthreads();
    int t = blockIdx.x * blockDim.x + threadIdx.x;
    int lane = threadIdx.x & 31;
    int q = t >> 2;
    int l4 = t & 3;
    float4 Q = g_b1[q];
    int p = g_qp[q];
    int s0 = soff[p], s1 = soff[p + 1];
    const float FINF = __int_as_float(0x7f800000);
    const float nnx = -2.f * Q.x, nny = -2.f * Q.y, nnz = -2.f * Q.z;
    float d0 = FINF, d1 = FINF, d2 = FINF, d3 = FINF;
    int j0 = -1, j1 = -1, j2 = -1, j3 = -1;
    int j = s0 + l4;
    for (; j + 4 < s1; j += 8) {
        float4 T = g_b2[j];
        float4 U = g_b2[j + 4];
        float d = fmaf(nnx, T.x, fmaf(nny, T.y, fmaf(nnz, T.z, T.w)));
        float e = fmaf(nnx, U.x, fmaf(nny, U.y, fmaf(nnz, U.z, U.w)));
        top4_ins(d, j, d0, d1, d2, d3, j0, j1, j2, j3);
        top4_ins(e, j + 4, d0, d1, d2, d3, j0, j1, j2, j3);
    }
    if (j < s1) {
        float4 T = g_b2[j];
        float d = fmaf(nnx, T.x, fmaf(nny, T.y, fmaf(nnz, T.z, T.w)));
        top4_ins(d, j, d0, d1, d2, d3, j0, j1, j2, j3);
    }
#pragma unroll
    for (int m = 1; m <= 2; m <<= 1) {
        float e0 = __shfl_xor_sync(0xffffffffu, d0, m);
        float e1 = __shfl_xor_sync(0xffffffffu, d1, m);
        float e2 = __shfl_xor_sync(0xffffffffu, d2, m);
        float e3 = __shfl_xor_sync(0xffffffffu, d3, m);
        int k0 = __shfl_xor_sync(0xffffffffu, j0, m);
        int k1 = __shfl_xor_sync(0xffffffffu, j1, m);
        int k2 = __shfl_xor_sync(0xffffffffu, j2, m);
        int k3 = __shfl_xor_sync(0xffffffffu, j3, m);
        top4_ins(e0, k0, d0, d1, d2, d3, j0, j1, j2, j3);
        top4_ins(e1, k1, d0, d1, d2, d3, j0, j1, j2, j3);
        top4_ins(e2, k2, d0, d1, d2, d3, j0, j1, j2, j3);
        top4_ins(e3, k3, d0, d1, d2, d3, j0, j1, j2, j3);
    }
    int fi0 = 0, fi1 = 0, fi2 = 0;
    float fw0 = 0.f, fw1 = 0.f, fw2 = 0.f;
    if (l4 == 0) {
        int cand[4] = { j0, j1, j2, j3 };
        float de[4];
#pragma unroll
        for (int c = 0; c < 4; c++) {
            if (cand[c] >= 0) {
                float4 T = g_b2[cand[c]];
                float dx = Q.x - T.x, dy = Q.y - T.y, dz = Q.z - T.z;
                de[c] = fmaf(dx, dx, fmaf(dy, dy, dz * dz));
            } else de[c] = FINF;
        }
#pragma unroll
        for (int r = 0; r < 3; r++) {
            int best = r;
#pragma unroll
            for (int c = r + 1; c < 4; c++) if (de[c] < de[best]) best = c;
            float td = de[r]; de[r] = de[best]; de[best] = td;
            int tj = cand[r]; cand[r] = cand[best]; cand[best] = tj;
        }
        fi0 = (cand[0] >= 0) ? g_b2i[cand[0]] : 0;
        fi1 = (cand[1] >= 0) ? g_b2i[cand[1]] : 0;
        fi2 = (cand[2] >= 0) ? g_b2i[cand[2]] : 0;
        float e0 = de[0], e1 = de[1], e2 = de[2];
        if (!(e0 < FINF)) { fi0 = 0;   e0 = BIGD; }
        if (!(e1 < FINF)) { fi1 = fi0; e1 = BIGD; }
        if (!(e2 < FINF)) { fi2 = fi0; e2 = BIGD; }
        float w0 = 1.0f / (e0 + WEPS);
        float w1 = 1.0f / (e1 + WEPS);
        float w2 = 1.0f / (e2 + WEPS);
        float inv = 1.0f / (w0 + w1 + w2);
        fw0 = w0 * inv; fw1 = w1 * inv; fw2 = w2 * inv;
    }
#pragma unroll 1
    for (int qi = 0; qi < 8; qi++) {
        int src = 4 * qi;
        int i0 = __shfl_sync(0xffffffffu, fi0, src);
        int i1 = __shfl_sync(0xffffffffu, fi1, src);
        int i2 = __shfl_sync(0xffffffffu, fi2, src);
        float w0 = __shfl_sync(0xffffffffu, fw0, src);
        float w1 = __shfl_sync(0xffffffffu, fw1, src);
        float w2 = __shfl_sync(0xffffffffu, fw2, src);
        int n = __shfl_sync(0xffffffffu, __float_as_int(Q.w), src);
        const float4* r0 = (const float4*)(g_f2t + (long)i0 * D2C);
        const float4* r1 = (const float4*)(g_f2t + (long)i1 * D2C);
        const float4* r2 = (const float4*)(g_f2t + (long)i2 * D2C);
#pragma unroll
        for (int c = lane; c < D2C / 4; c += 32) {
            float4 a = r0[c], b = r1[c], cc = r2[c];
            float4 v;
            v.x = w0 * a.x + w1 * b.x + w2 * cc.x;
            v.y = w0 * a.y + w1 * b.y + w2 * cc.y;
            v.z = w0 * a.z + w1 * b.z + w2 * cc.z;
            v.w = w0 * a.w + w1 * b.w + w2 * cc.w;
            uint2 hi, lo; split4h(v, hi, lo);
            long off = plane_off(NQ, n, 256 + 4 * c);
            *(uint2*)((char*)g_fAh + off) = hi;
            *(uint2*)((char*)g_fAl + off) = lo;
        }
    }
}

// ---------------- BN+ReLU+split of layer1 activations (feeds GEMM2) ----------
__global__ __launch_bounds__(256) void k_bnsplit(const float* __restrict__ Y) {
    int idx = blockIdx.x * 256 + threadIdx.x;
    int n = idx >> 5, k8 = (idx & 31) * 8;
    float4 v0 = *(const float4*)&Y[(long)n * COUT + k8];
    float4 v1 = *(const float4*)&Y[(long)n * COUT + k8 + 4];
    float4 sc0 = *(const float4*)&g_scale[k8],  sh0 = *(const float4*)&g_shift[k8];
    float4 sc1 = *(const float4*)&g_scale[k8 + 4], sh1 = *(const float4*)&g_shift[k8 + 4];
    v0.x = fmaxf(fmaf(v0.x, sc0.x, sh0.x), 0.f);
    v0.y = fmaxf(fmaf(v0.y, sc0.y, sh0.y), 0.f);
    v0.z = fmaxf(fmaf(v0.z, sc0.z, sh0.z), 0.f);
    v0.w = fmaxf(fmaf(v0.w, sc0.w, sh0.w), 0.f);
    v1.x = fmaxf(fmaf(v1.x, sc1.x, sh1.x), 0.f);
    v1.y = fmaxf(fmaf(v1.y, sc1.y, sh1.y), 0.f);
    v1.z = fmaxf(fmaf(v1.z, sc1.z, sh1.z), 0.f);
    v1.w = fmaxf(fmaf(v1.w, sc1.w, sh1.w), 0.f);
    uint2 h0, l0, h1, l1;
    split4h(v0, h0, l0);
    split4h(v1, h1, l1);
    long off = plane_off(NQ, n, k8);            // k8 8-aligned: 16B seg-aligned write
    *(uint4*)((char*)g_x1h + off) = make_uint4(h0.x, h0.y, h1.x, h1.y);
    *(uint4*)((char*)g_x1l + off) = make_uint4(l0.x, l0.y, l1.x, l1.y);
}

// ============================================================================
// HMMA fp16x2 GEMM: (Ah+Al)·Wh, cp.async.bulk fills (4-stage ring) + BN-finalize
// 512 threads / 16 warps, warp grid 4x4, warp tile 32x64. Grid 128 (R14 config).
// smem/stage: [Ah 8K][Al 8K][Wh 16K] = 32K; 4 stages.
// ============================================================================
#define HBUF 32768
#define HSMEM (1024 + 4 * HBUF)
#define NCTA (NQ / 128)          // 128

__device__ __forceinline__ void bulk_g2s(uint32_t dst, const void* src, uint32_t bytes,
                                         uint32_t mbar) {
    asm volatile(
        "cp.async.bulk.shared::cluster.global.mbarrier::complete_tx::bytes [%0], [%1], %2, [%3];"
        :: "r"(dst), "l"(src), "r"(bytes), "r"(mbar) : "memory");
}
__device__ __forceinline__ void mbar_wait(uint32_t addr, uint32_t parity) {
    asm volatile(
        "{\n\t.reg .pred P;\n"
        "LW_%=:\n\t"
        "mbarrier.try_wait.parity.acquire.cta.shared::cta.b64 P, [%0], %1, 0x989680;\n\t"
        "@P bra LD_%=;\n\t"
        "bra LW_%=;\n"
        "LD_%=:\n\t}"
        :: "r"(addr), "r"(parity) : "memory");
}
__device__ __forceinline__ void ldsm4(uint32_t* r, uint32_t addr) {
    asm volatile("ldmatrix.sync.aligned.m8n8.x4.shared.b16 {%0,%1,%2,%3}, [%4];"
                 : "=r"(r[0]), "=r"(r[1]), "=r"(r[2]), "=r"(r[3]) : "r"(addr));
}
__device__ __forceinline__ void mma16816(float* c, const uint32_t* a, uint32_t b0, uint32_t b1) {
    asm volatile(
        "mma.sync.aligned.m16n8k16.row.col.f32.f16.f16.f32 "
        "{%0,%1,%2,%3}, {%4,%5,%6,%7}, {%8,%9}, {%0,%1,%2,%3};"
        : "+f"(c[0]), "+f"(c[1]), "+f"(c[2]), "+f"(c[3])
        : "r"(a[0]), "r"(a[1]), "r"(a[2]), "r"(a[3]), "r"(b0), "r"(b1));
}

template<int KDIM>
__global__ __launch_bounds__(512, 1) void k_hmma(const __half* __restrict__ Ah,
                                                 const __half* __restrict__ Al,
                                                 const __half* __restrict__ Wh,
                                                 float* __restrict__ Y,
                                                 const float* __restrict__ gamma,
                                                 const float* __restrict__ beta,
                                                 int* __restrict__ sem) {
    extern __shared__ char sm[];
    const int tid = threadIdx.x;
    const int wid = tid >> 5, lid = tid & 31;
    const int wm = wid >> 2, wn = wid & 3;   // 4x4 warp grid, warp tile 32x64
    const int NCH = KDIM / 32;
    const uint32_t sbase = smem_u32(sm);

    if (tid == 0) {
#pragma unroll
        for (int s = 0; s < 4; s++)
            asm volatile("mbarrier.init.shared.b64 [%0], 1;" :: "r"(sbase + 8 * s) : "memory");
    }
    __syncthreads();

    const char* Ahg = (const char*)Ah + (long)blockIdx.x * 8192;   // + chunk*NQ*64
    const char* Alg = (const char*)Al + (long)blockIdx.x * 8192;
    const char* Whg = (const char*)Wh;                              // + chunk*16384

    const int aRow = wm * 32 + (lid & 15);
    const uint32_t aOff = (uint32_t)aRow * 64;
    const int xA = (aRow >> 1) & 3;
    const int segA = lid >> 4;
    const int bRow = wn * 64 + (lid & 7) + ((lid >> 4) & 1) * 8;
    const uint32_t bOff = (uint32_t)bRow * 64;
    const int xB = (bRow >> 1) & 3;
    const int segB = (lid >> 3) & 1;

    float acc[2][8][4];
#pragma unroll
    for (int i = 0; i < 2; i++)
#pragma unroll
        for (int jj = 0; jj < 8; jj++)
#pragma unroll
            for (int e = 0; e < 4; e++) acc[i][jj][e] = 0.f;

    auto issue = [&](int c) {
        if (tid == 0) {
            int b = c & 3;
            uint32_t sbuf = sbase + 1024 + (uint32_t)b * HBUF;
            uint32_t mb = sbase + 8 * (uint32_t)b;
            asm volatile("mbarrier.arrive.expect_tx.shared.b64 _, [%0], %1;"
                         :: "r"(mb), "r"(32768u) : "memory");
            bulk_g2s(sbuf,         Ahg + (long)c * (NQ * 64), 8192, mb);
            bulk_g2s(sbuf + 8192,  Alg + (long)c * (NQ * 64), 8192, mb);
            bulk_g2s(sbuf + 16384, Whg + (long)c * 16384, 16384, mb);
        }
    };

    issue(0); issue(1); issue(2);

    for (int c = 0; c < NCH; c++) {
        if (c) __syncthreads();                      // buffer (c+3)&3 fully consumed
        if (c + 3 < NCH) issue(c + 3);
        mbar_wait(sbase + 8 * (uint32_t)(c & 3), (uint32_t)((c >> 2) & 1));

        const uint32_t base = sbase + 1024 + (uint32_t)(c & 3) * HBUF;
#pragma unroll
        for (int ks = 0; ks < 2; ks++) {
            uint32_t aH[8], aL[8];
            const uint32_t aseg = (uint32_t)(((segA + 2 * ks) ^ xA) << 4);
#pragma unroll
            for (int mt = 0; mt < 2; mt++) {
                uint32_t a0 = base + aOff + (uint32_t)mt * 1024 + aseg;
                ldsm4(aH + 4 * mt, a0);
                ldsm4(aL + 4 * mt, a0 + 8192);
            }
            const uint32_t bseg = (uint32_t)(((segB + 2 * ks) ^ xB) << 4);
#pragma unroll
            for (int ng = 0; ng < 4; ng++) {
                uint32_t b0 = base + 16384 + bOff + (uint32_t)ng * 1024 + bseg;
                uint32_t bh[4];
                ldsm4(bh, b0);
#pragma unroll
                for (int mt = 0; mt < 2; mt++) {
                    mma16816(acc[mt][2 * ng],     aH + 4 * mt, bh[0], bh[1]);
                    mma16816(acc[mt][2 * ng + 1], aH + 4 * mt, bh[2], bh[3]);
                }
#pragma unroll
                for (int mt = 0; mt < 2; mt++) {
                    mma16816(acc[mt][2 * ng],     aL + 4 * mt, bh[0], bh[1]);
                    mma16816(acc[mt][2 * ng + 1], aL + 4 * mt, bh[2], bh[3]);
                }
            }
        }
    }
    __syncthreads();                                 // smem reuse below

    // ---- epilogue: store Y + BN partials (deterministic order) ----
    const int g = lid >> 2, t = lid & 3;
    const int rowbase = blockIdx.x * 128 + wm * 32;
    const int colbase = wn * 64;
#pragma unroll
    for (int mt = 0; mt < 2; mt++) {
#pragma unroll
        for (int nt = 0; nt < 8; nt++) {
            float* c = acc[mt][nt];
            long r0 = (long)(rowbase + mt * 16 + g) * COUT + colbase + nt * 8 + 2 * t;
            *(float2*)&Y[r0] = make_float2(c[0], c[1]);
            *(float2*)&Y[r0 + 8 * COUT] = make_float2(c[2], c[3]);
        }
    }
    float* sm_s = (float*)(sm + 1024);               // [4][256]
    float* sm_q = (float*)(sm + 1024 + 4096);
#pragma unroll
    for (int nt = 0; nt < 8; nt++) {
        float s0 = 0.f, s1 = 0.f, q0 = 0.f, q1 = 0.f;
#pragma unroll
        for (int mt = 0; mt < 2; mt++) {
            float* c = acc[mt][nt];
            s0 += c[0] + c[2];
            s1 += c[1] + c[3];
            q0 += c[0] * c[0] + c[2] * c[2];
            q1 += c[1] * c[1] + c[3] * c[3];
        }
#pragma unroll
        for (int m = 4; m <= 16; m <<= 1) {
            s0 += __shfl_xor_sync(0xffffffffu, s0, m);
            s1 += __shfl_xor_sync(0xffffffffu, s1, m);
            q0 += __shfl_xor_sync(0xffffffffu, q0, m);
            q1 += __shfl_xor_sync(0xffffffffu, q1, m);
        }
        if (g == 0) {
            int col = colbase + nt * 8 + 2 * t;
            sm_s[wm * 256 + col] = s0; sm_s[wm * 256 + col + 1] = s1;
            sm_q[wm * 256 + col] = q0; sm_q[wm * 256 + col + 1] = q1;
        }
    }
    __syncthreads();
    if (tid < 256) {
        g_ps[blockIdx.x * COUT + tid] = sm_s[tid] + sm_s[256 + tid] + sm_s[512 + tid] + sm_s[768 + tid];
        g_pq[blockIdx.x * COUT + tid] = sm_q[tid] + sm_q[256 + tid] + sm_q[512 + tid] + sm_q[768 + tid];
    }

    // ---- last-CTA BN finalize (deterministic fixed-order reduce) ----
    __shared__ int slast;
    __threadfence();
    __syncthreads();
    if (tid == 0) slast = (atomicAdd(sem, 1) == NCTA - 1);
    __syncthreads();
    if (slast && tid < 256) {
        __threadfence();
        float s = 0.f, q = 0.f;
#pragma unroll 4
        for (int b = 0; b < NCTA; b++) {
            s += g_ps[b * COUT + tid];
            q += g_pq[b * COUT + tid];
        }
        float mean = s * (1.0f / NQ);
        float var = q * (1.0f / NQ) - mean * mean;
        float rstd = rsqrtf(var + BNEPS);
        float sc = gamma[tid] * rstd;
        g_scale[tid] = sc;
        g_shift[tid] = beta[tid] - mean * sc;
        if (tid == 0) *sem = 0;
    }
}

// final: out[o*N + n] = relu(norm(y2[n][o])); also re-zeroes bucket counters
__global__ void k_outtrans(const float* __restrict__ Y, float* __restrict__ out) {
    __shared__ float tile[32][33];
    int n0 = blockIdx.x * 32, o0 = blockIdx.y * 32;
    int tx = threadIdx.x, ty = threadIdx.y;
    if (blockIdx.x == 0 && blockIdx.y == 0 && ty == 0 && tx < NP) {
        g_cnt1[tx] = 0; g_cnt2[tx] = 0; g_fill1[tx] = 0; g_fill2[tx] = 0;
    }
#pragma unroll
    for (int i = 0; i < 4; i++)
        tile[ty + 8 * i][tx] = Y[(long)(n0 + ty + 8 * i) * COUT + o0 + tx];
    __syncthreads();
#pragma unroll
    for (int i = 0; i < 4; i++) {
        int o = o0 + ty + 8 * i;
        float v = fmaf(tile[tx][ty + 8 * i], g_scale[o], g_shift[o]);
        out[(long)o * NQ + n0 + tx] = fmaxf(v, 0.f);
    }
}

// ---------------- launch ------------------------------------------------------
extern "C" void kernel_launch(void* const* d_in, const int* in_sizes, int n_in,
                              void* d_out, int out_size) {
    const float* xyz1 = (const float*)d_in[0];
    const float* xyz2 = (const float*)d_in[1];
    const int* pid1 = (const int*)d_in[2];
    const int* pid2 = (const int*)d_in[3];
    const float* points1 = (const float*)d_in[4];
    const float* points2 = (const float*)d_in[5];
    const float* w0 = (const float*)d_in[6];
    const float* gg0 = (const float*)d_in[8];
    const float* bt0 = (const float*)d_in[9];
    const float* w1 = (const float*)d_in[10];
    const float* gg1 = (const float*)d_in[12];
    const float* bt1 = (const float*)d_in[13];
    float* out = (float*)d_out;

    __half *p_fAh, *p_fAl, *p_x1h, *p_x1l, *p_wh;
    float *p_y, *p_y2;
    int *p_sem1, *p_sem2;
    cudaGetSymbolAddress((void**)&p_fAh, g_fAh);
    cudaGetSymbolAddress((void**)&p_fAl, g_fAl);
    cudaGetSymbolAddress((void**)&p_x1h, g_x1h);
    cudaGetSymbolAddress((void**)&p_x1l, g_x1l);
    cudaGetSymbolAddress((void**)&p_wh, g_wh);
    cudaGetSymbolAddress((void**)&p_y, g_y);
    cudaGetSymbolAddress((void**)&p_y2, g_y2);
    cudaGetSymbolAddress((void**)&p_sem1, g_sem1);
    cudaGetSymbolAddress((void**)&p_sem2, g_sem2);

    cudaFuncSetAttribute((const void*)k_hmma<CIN>,
                         cudaFuncAttributeMaxDynamicSharedMemorySize, HSMEM);
    cudaFuncSetAttribute((const void*)k_hmma<COUT>,
                         cudaFuncAttributeMaxDynamicSharedMemorySize, HSMEM);

    k_prep<<<PB_TOTAL, 256>>>(w0, w1, points1, points2, pid1, pid2);
    k_scatter<<<NQ / 256, 256>>>(xyz1, xyz2, pid1, pid2);
    k_knn_interp<<<(NQ * 4) / 256, 256>>>();

    // layer 1: 512 -> 256 (fp16x2; BN finalize fused) — idx 3 (profiled)
    k_hmma<CIN><<<NCTA, 512, HSMEM>>>(p_fAh, p_fAl, p_wh, p_y, gg0, bt0, p_sem1);
    // BN+ReLU+split layer1 activations into chunk-major fp16 planes
    k_bnsplit<<<NQ * COUT / 8 / 256, 256>>>(p_y);
    // layer 2: 256 -> 256
    k_hmma<COUT><<<NCTA, 512, HSMEM>>>(p_x1h, p_x1l,
                                       (__half*)((char*)p_wh + 262144),
                                       p_y2, gg1, bt1, p_sem2);
    k_outtrans<<<dim3(NQ / 32, COUT / 32), dim3(32, 8)>>>(p_y2, out);
}